// round 5
// baseline (speedup 1.0000x reference)
#include <cuda_runtime.h>

#define DIMC 192
#define RR   48
#define BB   4
#define HH   256
#define WW   256
#define HW   (HH * WW)
#define EPSV 1e-5f

__device__ float g_part[2 * BB * DIMC];      // partial pool sums
__device__ float g_wt[BB * DIMC * 4];        // 4 live taps per (b,c)

// ---------------------------------------------------------------------------
// Kernel 1: partial global average pool. Two blocks (512 thr) per channel.
// ---------------------------------------------------------------------------
__global__ void __launch_bounds__(512) pool_kernel(const float* __restrict__ x) {
    const int bc   = blockIdx.x >> 1;           // 0..767
    const int half = blockIdx.x & 1;            // 0/1
    const float4* p = (const float4*)(x + (size_t)bc * HW + (size_t)half * (HW / 2));
    const int n4 = HW / 8;                      // 8192 float4 per half
    float s0 = 0.f, s1 = 0.f;
    for (int i = threadIdx.x; i < n4; i += 1024) {
        float4 a = p[i];
        float4 b = p[i + 512];
        s0 += (a.x + a.y) + (a.z + a.w);
        s1 += (b.x + b.y) + (b.z + b.w);
    }
    float s = s0 + s1;
    #pragma unroll
    for (int o = 16; o > 0; o >>= 1) s += __shfl_xor_sync(0xffffffffu, s, o);
    __shared__ float sm[16];
    if ((threadIdx.x & 31) == 0) sm[threadIdx.x >> 5] = s;
    __syncthreads();
    if (threadIdx.x == 0) {
        float t = 0.f;
        #pragma unroll
        for (int i = 0; i < 16; i++) t += sm[i];
        g_part[blockIdx.x] = t;
    }
}

// ---------------------------------------------------------------------------
// Kernel 2: weight-gen MLP (tiny, single block).
// ---------------------------------------------------------------------------
__global__ void __launch_bounds__(256) wgen_kernel(
    const float* __restrict__ w1,
    const float* __restrict__ gamma, const float* __restrict__ beta,
    const float* __restrict__ rmean, const float* __restrict__ rvar,
    const float* __restrict__ w2,   const float* __restrict__ b2)
{
    __shared__ float s_pool[BB * DIMC];         // 768
    __shared__ float s_t[BB * RR];              // 192
    const int tid = threadIdx.x;

    for (int i = tid; i < BB * DIMC; i += 256)
        s_pool[i] = (g_part[2 * i] + g_part[2 * i + 1]) * (1.0f / (float)HW);
    __syncthreads();

    if (tid < BB * RR) {
        const int b = tid / RR;
        const int j = tid % RR;
        const float* pl = s_pool + b * DIMC;
        const float* wr = w1 + j * DIMC;
        float acc = 0.f;
        #pragma unroll 4
        for (int c = 0; c < DIMC; c++) acc = fmaf(pl[c], wr[c], acc);
        float v = gamma[j] * (acc - rmean[j]) * rsqrtf(rvar[j] + EPSV) + beta[j];
        s_t[tid] = fmaxf(v, 0.f);
    }
    __syncthreads();

    const int NKEPT = BB * DIMC * 4;            // 3072
    for (int idx = tid; idx < NKEPT; idx += 256) {
        const int b   = idx / (DIMC * 4);
        const int rem = idx % (DIMC * 4);
        const int c   = rem >> 2;
        const int tap = rem & 3;
        const int o   = c * 9 + tap;
        const float* tv = s_t + b * RR;
        const float* wr = w2 + o * RR;
        float acc = b2[o];
        #pragma unroll
        for (int j = 0; j < RR; j++) acc = fmaf(tv[j], wr[j], acc);
        g_wt[idx] = acc;
    }
}

// ---------------------------------------------------------------------------
// Kernel 3: 4-tap masked depthwise stencil + bias, rolling-register rows.
//   out[y][x] = w0*in[y-1][x-1] + w1*in[y-1][x] + w2*in[y-1][x+1]
//             + w3*in[y][x-1]   + bias[c]
// Block (64,4). Thread: 4-px strip, 8 rows. Tile = 32 rows. grid (8, 768).
// ---------------------------------------------------------------------------
__global__ void __launch_bounds__(256) conv_kernel(
    const float* __restrict__ x, const float* __restrict__ bias,
    float* __restrict__ out)
{
    const int bc   = blockIdx.y;
    const int c    = bc % DIMC;
    const int tx   = threadIdx.x;               // 0..63, x-contiguous in warp
    const int lane = tx & 31;
    const int x4   = tx * 4;
    const int r0   = blockIdx.x * 32 + threadIdx.y * 8;

    const float w0 = g_wt[bc * 4 + 0];
    const float w1 = g_wt[bc * 4 + 1];
    const float w2 = g_wt[bc * 4 + 2];
    const float w3 = g_wt[bc * 4 + 3];
    const float bv = bias[c];

    const float* in  = x   + (size_t)bc * HW;
    float*       ot  = out + (size_t)bc * HW;

    float4 pv; float pl, pr;
    if (r0 > 0) {
        const float* prv = in + (size_t)(r0 - 1) * WW;
        pv = *(const float4*)(prv + x4);
        pl = __shfl_up_sync(0xffffffffu, pv.w, 1);
        pr = __shfl_down_sync(0xffffffffu, pv.x, 1);
        if (lane == 0)  pl = (x4 > 0)      ? prv[x4 - 1] : 0.f;
        if (lane == 31) pr = (x4 + 4 < WW) ? prv[x4 + 4] : 0.f;
    } else {
        pv = make_float4(0.f, 0.f, 0.f, 0.f);
        pl = 0.f; pr = 0.f;
    }

    #pragma unroll
    for (int i = 0; i < 8; i++) {
        const int y = r0 + i;
        const float* cur = in + (size_t)y * WW;
        float4 cv = *(const float4*)(cur + x4);
        float cl = __shfl_up_sync(0xffffffffu, cv.w, 1);
        float cr = __shfl_down_sync(0xffffffffu, cv.x, 1);
        if (lane == 0)  cl = (x4 > 0)      ? cur[x4 - 1] : 0.f;
        if (lane == 31) cr = (x4 + 4 < WW) ? cur[x4 + 4] : 0.f;

        float4 o;
        o.x = fmaf(w0, pl,   fmaf(w1, pv.x, fmaf(w2, pv.y, fmaf(w3, cl,   bv))));
        o.y = fmaf(w0, pv.x, fmaf(w1, pv.y, fmaf(w2, pv.z, fmaf(w3, cv.x, bv))));
        o.z = fmaf(w0, pv.y, fmaf(w1, pv.z, fmaf(w2, pv.w, fmaf(w3, cv.y, bv))));
        o.w = fmaf(w0, pv.z, fmaf(w1, pv.w, fmaf(w2, pr,   fmaf(w3, cv.z, bv))));

        *(float4*)(ot + (size_t)y * WW + x4) = o;

        pv = cv; pl = cl; pr = cr;
    }
}

// ---------------------------------------------------------------------------
extern "C" void kernel_launch(void* const* d_in, const int* in_sizes, int n_in,
                              void* d_out, int out_size)
{
    const float* x     = (const float*)d_in[0];
    const float* w1    = (const float*)d_in[1];
    const float* gamma = (const float*)d_in[2];
    const float* beta  = (const float*)d_in[3];
    const float* rmean = (const float*)d_in[4];
    const float* rvar  = (const float*)d_in[5];
    const float* w2    = (const float*)d_in[6];
    const float* b2    = (const float*)d_in[7];
    const float* bias  = (const float*)d_in[8];
    float* out = (float*)d_out;

    pool_kernel<<<2 * BB * DIMC, 512>>>(x);
    wgen_kernel<<<1, 256>>>(w1, gamma, beta, rmean, rvar, w2, b2);
    dim3 blk(64, 4);
    dim3 grd(8, BB * DIMC);
    conv_kernel<<<grd, blk>>>(x, bias, out);
}